// round 13
// baseline (speedup 1.0000x reference)
#include <cuda_runtime.h>
#include <stdint.h>
#include <math.h>

#define Tq 1024
#define Bq 8
#define Dq 1024
#define NH 16
#define DH 64
#define TB (Tq*Bq)       /* 8192 rows */
#define ND (NH*DH)       /* 1024 */
#define N3 (3*ND)        /* 3072 */
#define ZN (Bq*NH)       /* 128 */

// ---- static scratch (zero-initialized; masked region of g_S never written) ----
__device__ float g_x[(size_t)TB*Dq];        // rounded x, k-permuted
__device__ float g_wqT[(size_t)N3*Dq];      // rounded W_qkv^T [n][k], k-permuted
__device__ float g_woT[(size_t)ND*ND];      // rounded W_o^T  [n][k], k-permuted
__device__ float g_q[(size_t)ZN*Tq*DH];     // rounded, [b][n][t][d], d-permuted
__device__ float g_k[(size_t)ZN*Tq*DH];     // rounded, d-permuted
__device__ float g_v[(size_t)ZN*Tq*DH];     // rounded, natural d
__device__ float g_av[(size_t)TB*ND];       // [t*B+b][col], col-permuted
__device__ float g_S[(size_t)ZN*Tq*Tq];     // probs (tf32-rounded), masked = 0

// ---- helpers ----
__device__ __forceinline__ uint32_t f2tf(float x) {
    uint32_t y;
    asm("cvt.rna.tf32.f32 %0, %1;" : "=r"(y) : "f"(x));
    return y;
}
__device__ __forceinline__ float f2tf_f(float x) { return __uint_as_float(f2tf(x)); }
__device__ __forceinline__ int perm8(int x) { return 2 * (x & 3) + (x >> 2); } // x in 0..7
__device__ __forceinline__ void mma8(float c[4],
                                     uint32_t a0, uint32_t a1, uint32_t a2, uint32_t a3,
                                     uint32_t b0, uint32_t b1) {
    asm volatile("mma.sync.aligned.m16n8k8.row.col.f32.tf32.tf32.f32 "
                 "{%0,%1,%2,%3}, {%4,%5,%6,%7}, {%8,%9}, {%0,%1,%2,%3};\n"
                 : "+f"(c[0]), "+f"(c[1]), "+f"(c[2]), "+f"(c[3])
                 : "r"(a0), "r"(a1), "r"(a2), "r"(a3), "r"(b0), "r"(b1));
}
#define CP16(dst_u32, src_ptr) \
    asm volatile("cp.async.cg.shared.global [%0], [%1], 16;\n" :: "r"(dst_u32), "l"(src_ptr))
#define CP_COMMIT() asm volatile("cp.async.commit_group;\n")
#define CP_WAIT(n)  asm volatile("cp.async.wait_group %0;\n" :: "n"(n))

// ============================================================================
// x = tf32(input + pos_enc), stored with k-pair permutation. 8 elems/thread.
// ============================================================================
__global__ __launch_bounds__(256) void add_kernel(const float* __restrict__ a,
                                                  const float* __restrict__ b) {
    size_t i = ((size_t)blockIdx.x * 256 + threadIdx.x) * 8;
    float4 a0 = *(const float4*)(a + i),     a1 = *(const float4*)(a + i + 4);
    float4 b0 = *(const float4*)(b + i),     b1 = *(const float4*)(b + i + 4);
    float r0 = f2tf_f(a0.x + b0.x), r1 = f2tf_f(a0.y + b0.y);
    float r2 = f2tf_f(a0.z + b0.z), r3 = f2tf_f(a0.w + b0.w);
    float r4 = f2tf_f(a1.x + b1.x), r5 = f2tf_f(a1.y + b1.y);
    float r6 = f2tf_f(a1.z + b1.z), r7 = f2tf_f(a1.w + b1.w);
    float4 o0 = {r0, r4, r1, r5};
    float4 o1 = {r2, r6, r3, r7};
    *(float4*)(g_x + i) = o0;
    *(float4*)(g_x + i + 4) = o1;
}

// ============================================================================
// Transpose + round + k-permute weights:  dst[n][k'] = tf32(src[k][n])
// ============================================================================
template<int NCOLS>
__device__ __forceinline__ void transpose_round(const float* __restrict__ src,
                                                float* __restrict__ dst) {
    __shared__ float sm[32][33];
    const int t = threadIdx.x;
    const int k0 = blockIdx.y * 32, n0 = blockIdx.x * 32;
    {
        int kk = t >> 3, nn = (t & 7) * 4;
        float4 v = *(const float4*)(src + (size_t)(k0 + kk) * NCOLS + n0 + nn);
        sm[kk][nn] = v.x; sm[kk][nn + 1] = v.y; sm[kk][nn + 2] = v.z; sm[kk][nn + 3] = v.w;
    }
    __syncthreads();
    {
        int nrow = t >> 3;
        int q = t & 7, gg = q >> 1, h = q & 1;
        int o0 = h ? 2 : 0, o1 = h ? 6 : 4, o2 = h ? 3 : 1, o3 = h ? 7 : 5;
        int kb = gg * 8;
        float4 o;
        o.x = f2tf_f(sm[kb + o0][nrow]);
        o.y = f2tf_f(sm[kb + o1][nrow]);
        o.z = f2tf_f(sm[kb + o2][nrow]);
        o.w = f2tf_f(sm[kb + o3][nrow]);
        *(float4*)(dst + (size_t)(n0 + nrow) * 1024 + k0 + kb + h * 4) = o;
    }
}
__global__ __launch_bounds__(256) void round_wq(const float* __restrict__ src) {
    transpose_round<N3>(src, g_wqT);
}
__global__ __launch_bounds__(256) void round_wo(const float* __restrict__ src) {
    transpose_round<ND>(src, g_woT);
}

// ============================================================================
// tf32 GEMM body, cp.async 2-stage, LDS.64 pair fragments. (R9-identical)
// ============================================================================
#define T_STG 5120   /* 128*40 floats per stage (A or B) */
#define NSTG  2
#define GEMM_SMEM (NSTG * 2 * T_STG * 4)   /* 81920 bytes */

struct GemmFrag { float acc[4][4][4]; };

__device__ __forceinline__ void gemm_issue(uint32_t aB, uint32_t bB, int s,
                                           const float* __restrict__ Ag,
                                           const float* __restrict__ Bg,
                                           int ldA, int ldB, int m0, int n0, int k0,
                                           int tx) {
#pragma unroll
    for (int p = 0; p < 4; p++) {
        int chunk = tx + p * 256;
        int row = chunk >> 3;
        int coff = (chunk & 7) * 4;
        CP16(aB + (uint32_t)(s * T_STG + row * 40 + coff) * 4u,
             Ag + (size_t)(m0 + row) * ldA + k0 + coff);
        CP16(bB + (uint32_t)(s * T_STG + row * 40 + coff) * 4u,
             Bg + (size_t)(n0 + row) * ldB + k0 + coff);
    }
}

__device__ __forceinline__ void gemm_compute(GemmFrag& F, const uint32_t* Asm,
                                             const uint32_t* Bsm, int s,
                                             int wm, int wn, int g, int tg) {
    const uint32_t* A = Asm + s * T_STG;
    const uint32_t* B = Bsm + s * T_STG;
#pragma unroll
    for (int ks = 0; ks < 32; ks += 8) {
        uint32_t a[4][4], b[4][2];
#pragma unroll
        for (int mi = 0; mi < 4; mi++) {
            int r = wm + mi * 16 + g;
            uint2 p0 = *(const uint2*)&A[r * 40 + ks + 2 * tg];
            uint2 p1 = *(const uint2*)&A[(r + 8) * 40 + ks + 2 * tg];
            a[mi][0] = p0.x; a[mi][2] = p0.y;
            a[mi][1] = p1.x; a[mi][3] = p1.y;
        }
#pragma unroll
        for (int ni = 0; ni < 4; ni++) {
            int c = wn + ni * 8 + g;
            uint2 pb = *(const uint2*)&B[c * 40 + ks + 2 * tg];
            b[ni][0] = pb.x; b[ni][1] = pb.y;
        }
#pragma unroll
        for (int mi = 0; mi < 4; mi++)
#pragma unroll
            for (int ni = 0; ni < 4; ni++)
                mma8(F.acc[mi][ni], a[mi][0], a[mi][1], a[mi][2], a[mi][3],
                     b[ni][0], b[ni][1]);
    }
}

#define GEMM_MAINLOOP(Ag, Bg, ldA, ldB)                                         \
    gemm_issue(aB, bB, 0, Ag, Bg, ldA, ldB, m0, n0, 0, tx);                     \
    CP_COMMIT();                                                                \
    { int buf = 0;                                                              \
    _Pragma("unroll 1")                                                         \
    for (int it = 0; it < 32; it++) {                                           \
        if (it + 1 < 32) {                                                      \
            gemm_issue(aB, bB, buf ^ 1, Ag, Bg, ldA, ldB, m0, n0,               \
                       (it + 1) * 32, tx);                                      \
            CP_COMMIT();                                                        \
            CP_WAIT(1);                                                         \
        } else {                                                                \
            CP_WAIT(0);                                                         \
        }                                                                       \
        __syncthreads();                                                        \
        gemm_compute(F, Asm, Bsm, buf, wm, wn, g, tg);                          \
        __syncthreads();                                                        \
        buf ^= 1;                                                               \
    } }

// ============================================================================
// QKV GEMM: [8192,3072] = g_x @ g_wqT^T; scatter rounded Q/K/V.
// ============================================================================
__global__ __launch_bounds__(256, 2) void qkv_gemm() {
    extern __shared__ float sm[];
    const uint32_t* Asm = (const uint32_t*)sm;
    const uint32_t* Bsm = (const uint32_t*)(sm + NSTG * T_STG);
    uint32_t aB = (uint32_t)__cvta_generic_to_shared(sm);
    uint32_t bB = (uint32_t)__cvta_generic_to_shared(sm + NSTG * T_STG);
    const int tx = threadIdx.x;
    const int warp = tx >> 5, lane = tx & 31;
    const int g = lane >> 2, tg = lane & 3;
    const int wm = (warp >> 2) * 64, wn = (warp & 3) * 32;
    const int m0 = blockIdx.y * 128, n0 = blockIdx.x * 128;

    GemmFrag F;
#pragma unroll
    for (int mi = 0; mi < 4; mi++)
#pragma unroll
        for (int ni = 0; ni < 4; ni++)
#pragma unroll
            for (int r = 0; r < 4; r++) F.acc[mi][ni][r] = 0.f;

    GEMM_MAINLOOP(g_x, g_wqT, Dq, Dq)

#pragma unroll
    for (int mi = 0; mi < 4; mi++)
#pragma unroll
        for (int ni = 0; ni < 4; ni++)
#pragma unroll
            for (int rr = 0; rr < 2; rr++) {
                int row = m0 + wm + mi * 16 + g + rr * 8;
                int b = row & 7, t = row >> 3;
#pragma unroll
                for (int cc = 0; cc < 2; cc++) {
                    int col = n0 + wn + ni * 8 + 2 * tg + cc;
                    int part = col >> 10;
                    int rem = col & 1023;
                    int n = rem >> 6, d = rem & 63;
                    float val = f2tf_f(F.acc[mi][ni][rr * 2 + cc]);
                    size_t base = ((size_t)((b << 4) + n) * Tq + t) * DH;
                    if (part == 0)       g_q[base + (d & ~7) + perm8(d & 7)] = val;
                    else if (part == 1)  g_k[base + (d & ~7) + perm8(d & 7)] = val;
                    else                 g_v[base + d] = val;
                }
            }
}

// ============================================================================
// Output projection: out[8192,1024] = g_av @ g_woT^T, STG.64 epilogue.
// ============================================================================
__global__ __launch_bounds__(256, 2) void out_gemm(float* __restrict__ out) {
    extern __shared__ float sm[];
    const uint32_t* Asm = (const uint32_t*)sm;
    const uint32_t* Bsm = (const uint32_t*)(sm + NSTG * T_STG);
    uint32_t aB = (uint32_t)__cvta_generic_to_shared(sm);
    uint32_t bB = (uint32_t)__cvta_generic_to_shared(sm + NSTG * T_STG);
    const int tx = threadIdx.x;
    const int warp = tx >> 5, lane = tx & 31;
    const int g = lane >> 2, tg = lane & 3;
    const int wm = (warp >> 2) * 64, wn = (warp & 3) * 32;
    const int m0 = blockIdx.y * 128, n0 = blockIdx.x * 128;

    GemmFrag F;
#pragma unroll
    for (int mi = 0; mi < 4; mi++)
#pragma unroll
        for (int ni = 0; ni < 4; ni++)
#pragma unroll
            for (int r = 0; r < 4; r++) F.acc[mi][ni][r] = 0.f;

    GEMM_MAINLOOP(g_av, g_woT, ND, ND)

#pragma unroll
    for (int mi = 0; mi < 4; mi++)
#pragma unroll
        for (int ni = 0; ni < 4; ni++)
#pragma unroll
            for (int rr = 0; rr < 2; rr++) {
                int row = m0 + wm + mi * 16 + g + rr * 8;
                int col = n0 + wn + ni * 8 + 2 * tg;
                float2 v = { F.acc[mi][ni][rr * 2], F.acc[mi][ni][rr * 2 + 1] };
                *(float2*)(out + (size_t)row * ND + col) = v;
            }
}

// ============================================================================
// Scores + FUSED SOFTMAX. CTA per (z, 64-row i-tile): Q persistent, K-tiles
// 2-stage cp.async (tj = 0..ti). After the mainloop the CTA's 64 rows are
// complete in g_S (hot in L2) -> each warp softmaxes 8 rows in place and
// writes tf32-rounded probs. Same numeric path as separate kernels ->
// bit-identical g_S.
// ============================================================================
#define SCT (64*72)
#define SC_SMEM (3 * SCT * 4)   /* 55296 bytes */

__global__ __launch_bounds__(256, 2) void score_kernel() {
    extern __shared__ float sm[];
    uint32_t* Qs = (uint32_t*)sm;            // [64][72]
    float* Kf = sm + SCT;                    // 2 stages of [64][72]
    uint32_t kB = (uint32_t)__cvta_generic_to_shared(Kf);

    const int ti = (Tq / 64 - 1) - blockIdx.x;   // heavy tiles first
    const int z = blockIdx.y;
    const int tx = threadIdx.x;
    const int warp = tx >> 5, lane = tx & 31;
    const int g = lane >> 2, tg = lane & 3;
    const int wm = (warp >> 2) * 32;
    const int wn = (warp & 3) * 16;

    const int lrow = tx >> 2, lcol = (tx & 3) * 16;
    const float* kbase = g_k + ((size_t)z * Tq + lrow) * DH + lcol;

    const int nj = ti + 1;

    // prologue: K stage 0 <- tj 0
#pragma unroll
    for (int q = 0; q < 4; q++)
        CP16(kB + (uint32_t)(lrow * 72 + lcol + q * 4) * 4u, kbase + q * 4);
    CP_COMMIT();

    // persistent Q tile (pre-rounded, d-permuted -> raw uint4 copies)
    {
        const float* qb = g_q + ((size_t)z * Tq + ti * 64) * DH;
        const int lr = tx >> 2, lc0 = (tx & 3) << 2;
#pragma unroll
        for (int rr = 0; rr < 4; rr++) {
            int c = lc0 + rr * 16;
            *(uint4*)&Qs[lr * 72 + c] = *(const uint4*)(qb + lr * DH + c);
        }
    }

    int buf = 0;
#pragma unroll 1
    for (int tj = 0; tj < nj; tj++) {
        if (tj + 1 < nj) {
            int s = buf ^ 1;
#pragma unroll
            for (int q = 0; q < 4; q++)
                CP16(kB + (uint32_t)(s * SCT + lrow * 72 + lcol + q * 4) * 4u,
                     kbase + (size_t)(tj + 1) * 64 * DH + q * 4);
            CP_COMMIT();
            CP_WAIT(1);
        } else {
            CP_WAIT(0);
        }
        __syncthreads();

        const uint32_t* K = (const uint32_t*)(Kf + buf * SCT);

        float acc[2][2][4];
#pragma unroll
        for (int mi = 0; mi < 2; mi++)
#pragma unroll
            for (int ni = 0; ni < 2; ni++)
#pragma unroll
                for (int r = 0; r < 4; r++) acc[mi][ni][r] = 0.f;

#pragma unroll
        for (int ks = 0; ks < 64; ks += 8) {
            uint32_t a[2][4], b[2][2];
#pragma unroll
            for (int mi = 0; mi < 2; mi++) {
                int r = wm + mi * 16 + g;
                uint2 p0 = *(const uint2*)&Qs[r * 72 + ks + 2 * tg];
                uint2 p1 = *(const uint2*)&Qs[(r + 8) * 72 + ks + 2 * tg];
                a[mi][0] = p0.x; a[mi][2] = p0.y;
                a[mi][1] = p1.x; a[mi][3] = p1.y;
            }
#pragma unroll
            for (int ni = 0; ni < 2; ni++) {
                int c = wn + ni * 8 + g;
                uint2 pb = *(const uint2*)&K[c * 72 + ks + 2 * tg];
                b[ni][0] = pb.x; b[ni][1] = pb.y;
            }
#pragma unroll
            for (int mi = 0; mi < 2; mi++)
#pragma unroll
                for (int ni = 0; ni < 2; ni++)
                    mma8(acc[mi][ni], a[mi][0], a[mi][1], a[mi][2], a[mi][3],
                         b[ni][0], b[ni][1]);
        }

        const float scale = 0.125f;
        if (tj < ti) {
#pragma unroll
            for (int mi = 0; mi < 2; mi++)
#pragma unroll
                for (int ni = 0; ni < 2; ni++)
#pragma unroll
                    for (int rr = 0; rr < 2; rr++) {
                        int i = ti * 64 + wm + mi * 16 + g + rr * 8;
                        int j = tj * 64 + wn + ni * 8 + 2 * tg;
                        float2 v = { acc[mi][ni][rr * 2] * scale,
                                     acc[mi][ni][rr * 2 + 1] * scale };
                        *(float2*)(g_S + ((size_t)z * Tq + i) * Tq + j) = v;
                    }
        } else {
#pragma unroll
            for (int mi = 0; mi < 2; mi++)
#pragma unroll
                for (int ni = 0; ni < 2; ni++)
#pragma unroll
                    for (int rr = 0; rr < 2; rr++) {
                        int i = ti * 64 + wm + mi * 16 + g + rr * 8;
#pragma unroll
                        for (int cc = 0; cc < 2; cc++) {
                            int j = tj * 64 + wn + ni * 8 + 2 * tg + cc;
                            if (j <= i)
                                g_S[((size_t)z * Tq + i) * Tq + j] =
                                    acc[mi][ni][rr * 2 + cc] * scale;
                        }
                    }
        }
        __syncthreads();
        buf ^= 1;
    }

    // ==== fused softmax: warp w handles rows w*8 .. w*8+7 of this block ====
    __syncthreads();   // all score STGs visible CTA-wide
#pragma unroll 1
    for (int rr = 0; rr < 8; rr++) {
        const int i = ti * 64 + warp * 8 + rr;
        const int len = i + 1;
        float* row = g_S + ((size_t)z * Tq + i) * Tq;

        float vals[4][8];
        float m = -1e30f;
#pragma unroll
        for (int p = 0; p < 4; p++) {
            int j0 = p * 256 + lane * 8;
            if (j0 < len) {
                float4 v0 = *(const float4*)(row + j0);
                float4 v1 = *(const float4*)(row + j0 + 4);
                vals[p][0] = v0.x; vals[p][1] = v0.y; vals[p][2] = v0.z; vals[p][3] = v0.w;
                vals[p][4] = v1.x; vals[p][5] = v1.y; vals[p][6] = v1.z; vals[p][7] = v1.w;
#pragma unroll
                for (int u = 0; u < 8; u++)
                    if (j0 + u < len) m = fmaxf(m, vals[p][u]);
            } else {
#pragma unroll
                for (int u = 0; u < 8; u++) vals[p][u] = -1e30f;
            }
        }
#pragma unroll
        for (int o = 16; o; o >>= 1) m = fmaxf(m, __shfl_xor_sync(0xffffffffu, m, o));

        float s = 0.f;
#pragma unroll
        for (int p = 0; p < 4; p++) {
            int j0 = p * 256 + lane * 8;
#pragma unroll
            for (int u = 0; u < 8; u++) {
                float e = __expf(vals[p][u] - m);
                vals[p][u] = e;
                if (j0 + u < len) s += e;
            }
        }
#pragma unroll
        for (int o = 16; o; o >>= 1) s += __shfl_xor_sync(0xffffffffu, s, o);
        const float inv = 1.0f / s;

#pragma unroll
        for (int p = 0; p < 4; p++) {
            int j0 = p * 256 + lane * 8;
            if (j0 + 8 <= len) {
                float4 o0, o1;
                o0.x = f2tf_f(vals[p][0] * inv); o0.y = f2tf_f(vals[p][1] * inv);
                o0.z = f2tf_f(vals[p][2] * inv); o0.w = f2tf_f(vals[p][3] * inv);
                o1.x = f2tf_f(vals[p][4] * inv); o1.y = f2tf_f(vals[p][5] * inv);
                o1.z = f2tf_f(vals[p][6] * inv); o1.w = f2tf_f(vals[p][7] * inv);
                *(float4*)(row + j0) = o0;
                *(float4*)(row + j0 + 4) = o1;
            } else if (j0 < len) {
#pragma unroll
                for (int u = 0; u < 8; u++)
                    if (j0 + u < len) row[j0 + u] = f2tf_f(vals[p][u] * inv);
            }
        }
    }
}

// ============================================================================
// Coverage: out[b][j][i] = mean_n prob[b][n][i][j]. (unchanged)
// ============================================================================
__global__ __launch_bounds__(256) void coverage_kernel(float* __restrict__ out_cov) {
    const int b = blockIdx.z;
    const int i0 = blockIdx.y * 32, j0 = blockIdx.x * 32;
    const int tx = threadIdx.x;

    if (j0 >= i0 + 32) {
#pragma unroll
        for (int it = 0; it < 4; it++) {
            int idx = tx + it * 256;
            int jj = idx >> 5, ii = idx & 31;
            out_cov[((size_t)b * Tq + j0 + jj) * Tq + i0 + ii] = 0.f;
        }
        return;
    }

    __shared__ float cs[32][33];
#pragma unroll
    for (int it = 0; it < 4; it++) {
        int idx = tx + it * 256;
        int ii = idx >> 5, jj = idx & 31;
        float s = 0.f;
#pragma unroll
        for (int n = 0; n < 16; n++)
            s += g_S[(((size_t)(b * 16 + n) * Tq + i0 + ii) * Tq) + j0 + jj];
        cs[ii][jj] = s * (1.0f / 16.0f);
    }
    __syncthreads();
#pragma unroll
    for (int it = 0; it < 4; it++) {
        int idx = tx + it * 256;
        int jj = idx >> 5, ii = idx & 31;
        out_cov[((size_t)b * Tq + j0 + jj) * Tq + i0 + ii] = cs[ii][jj];
    }
}

// ============================================================================
// PV: attn_vec = P @ V, cp.async 2-stage, cvt-free mainloop. (R12-identical)
// ============================================================================
#define AVP 4352   /* 64*68 floats per stage */
#define AVV 4608   /* 64*72 floats per stage */
#define AV_SMEM ((2*AVP + 2*AVV) * 4)   /* 71680 bytes */

__global__ __launch_bounds__(256, 2) void av_kernel() {
    extern __shared__ float sm[];
    float* Pf = sm;
    float* Vf = sm + 2 * AVP;
    uint32_t pB = (uint32_t)__cvta_generic_to_shared(Pf);
    uint32_t vB = (uint32_t)__cvta_generic_to_shared(Vf);

    const int ti = (Tq / 64 - 1) - blockIdx.x;   // heavy tiles first
    const int z = blockIdx.y;
    const int bq = z >> 4, nh = z & 15;
    const int tx = threadIdx.x;
    const int warp = tx >> 5, lane = tx & 31;
    const int g = lane >> 2, tg = lane & 3;
    const int wm = (warp >> 2) * 32;
    const int wn = (warp & 3) * 16;

    const int lrow = tx >> 2, lcol = (tx & 3) * 16;
    const float* pbase = g_S + ((size_t)z * Tq + ti * 64 + lrow) * Tq + lcol;
    const float* vbase = g_v + ((size_t)z * Tq + lrow) * DH + lcol;

    const int nj = ti + 1;

    float acc[2][2][4];
#pragma unroll
    for (int mi = 0; mi < 2; mi++)
#pragma unroll
        for (int ni = 0; ni < 2; ni++)
#pragma unroll
            for (int r = 0; r < 4; r++) acc[mi][ni][r] = 0.f;

#pragma unroll
    for (int q = 0; q < 4; q++) {
        CP16(pB + (uint32_t)(lrow * 68 + lcol + q * 4) * 4u, pbase + q * 4);
        CP16(vB + (uint32_t)(lrow * 72 + lcol + q * 4) * 4u, vbase + q * 4);
    }
    CP_COMMIT();

    int buf = 0;
#pragma unroll 1
    for (int jt = 0; jt < nj; jt++) {
        if (jt + 1 < nj) {
            int s = buf ^ 1;
            int jn = jt + 1;
#pragma unroll
            for (int q = 0; q < 4; q++) {
                CP16(pB + (uint32_t)(s * AVP + lrow * 68 + lcol + q * 4) * 4u,
                     pbase + jn * 64 + q * 4);
                CP16(vB + (uint32_t)(s * AVV + lrow * 72 + lcol + q * 4) * 4u,
                     vbase + (size_t)jn * 64 * DH + q * 4);
            }
            CP_COMMIT();
            CP_WAIT(1);
        } else {
            CP_WAIT(0);
        }
        __syncthreads();

        const uint32_t* P = (const uint32_t*)(Pf + buf * AVP);
        const uint32_t* V = (const uint32_t*)(Vf + buf * AVV);
#pragma unroll
        for (int ks = 0; ks < 64; ks += 8) {
            uint32_t a[2][4], b[2][2];
#pragma unroll
            for (int mi = 0; mi < 2; mi++) {
                int r = wm + mi * 16 + g;
                a[mi][0] = P[r * 68 + ks + tg];
                a[mi][1] = P[(r + 8) * 68 + ks + tg];
                a[mi][2] = P[r * 68 + ks + tg + 4];
                a[mi][3] = P[(r + 8) * 68 + ks + tg + 4];
            }
#pragma unroll
            for (int ni = 0; ni < 2; ni++) {
                int c = wn + ni * 8 + g;
                b[ni][0] = V[(ks + tg) * 72 + c];
                b[ni][1] = V[(ks + tg + 4) * 72 + c];
            }
#pragma unroll
            for (int mi = 0; mi < 2; mi++)
#pragma unroll
                for (int ni = 0; ni < 2; ni++)
                    mma8(acc[mi][ni], a[mi][0], a[mi][1], a[mi][2], a[mi][3],
                         b[ni][0], b[ni][1]);
        }
        __syncthreads();
        buf ^= 1;
    }

#pragma unroll
    for (int mi = 0; mi < 2; mi++)
#pragma unroll
        for (int ni = 0; ni < 2; ni++)
#pragma unroll
            for (int rr = 0; rr < 2; rr++) {
                int i = ti * 64 + wm + mi * 16 + g + rr * 8;
#pragma unroll
                for (int cc = 0; cc < 2; cc++) {
                    int d = wn + ni * 8 + 2 * tg + cc;
                    int dp = (d & ~7) + perm8(d & 7);
                    g_av[((size_t)(i * Bq + bq)) * ND + nh * 64 + dp] = acc[mi][ni][rr * 2 + cc];
                }
            }
}

// ============================================================================
extern "C" void kernel_launch(void* const* d_in, const int* in_sizes, int n_in,
                              void* d_out, int out_size) {
    const float* inp  = (const float*)d_in[0];
    const float* pe   = (const float*)d_in[1];
    const float* Wqkv = (const float*)d_in[3];
    const float* Wo   = (const float*)d_in[4];

    float* out_attn = (float*)d_out;
    float* out_cov  = out_attn + (size_t)TB * ND;

    cudaFuncSetAttribute(qkv_gemm, cudaFuncAttributeMaxDynamicSharedMemorySize, GEMM_SMEM);
    cudaFuncSetAttribute(out_gemm, cudaFuncAttributeMaxDynamicSharedMemorySize, GEMM_SMEM);
    cudaFuncSetAttribute(av_kernel, cudaFuncAttributeMaxDynamicSharedMemorySize, AV_SMEM);
    cudaFuncSetAttribute(score_kernel, cudaFuncAttributeMaxDynamicSharedMemorySize, SC_SMEM);

    add_kernel<<<TB * Dq / 2048, 256>>>(inp, pe);
    round_wq<<<dim3(N3 / 32, Dq / 32), 256>>>(Wqkv);
    round_wo<<<dim3(ND / 32, ND / 32), 256>>>(Wo);
    qkv_gemm<<<dim3(N3 / 128, TB / 128), 256, GEMM_SMEM>>>();
    score_kernel<<<dim3(Tq / 64, ZN), 256, SC_SMEM>>>();
    coverage_kernel<<<dim3(Tq / 32, Tq / 32, Bq), 256>>>(out_cov);
    av_kernel<<<dim3(Tq / 64, ZN), 256, AV_SMEM>>>();
    out_gemm<<<dim3(ND / 128, TB / 128), 256, GEMM_SMEM>>>(out_attn);
}

// round 14
// speedup vs baseline: 1.0137x; 1.0137x over previous
#include <cuda_runtime.h>
#include <stdint.h>
#include <math.h>

#define Tq 1024
#define Bq 8
#define Dq 1024
#define NH 16
#define DH 64
#define TB (Tq*Bq)       /* 8192 rows */
#define ND (NH*DH)       /* 1024 */
#define N3 (3*ND)        /* 3072 */
#define ZN (Bq*NH)       /* 128 */

// ---- static scratch (zero-initialized; masked region of g_S never written) ----
__device__ float g_x[(size_t)TB*Dq];        // rounded x, k-permuted
__device__ float g_wqT[(size_t)N3*Dq];      // rounded W_qkv^T [n][k], k-permuted
__device__ float g_woT[(size_t)ND*ND];      // rounded W_o^T  [n][k], k-permuted
__device__ float g_q[(size_t)ZN*Tq*DH];     // rounded, [b][n][t][d], d-permuted
__device__ float g_k[(size_t)ZN*Tq*DH];     // rounded, d-permuted
__device__ float g_v[(size_t)ZN*Tq*DH];     // rounded, natural d
__device__ float g_av[(size_t)TB*ND];       // [t*B+b][col], col-permuted
__device__ float g_S[(size_t)ZN*Tq*Tq];     // probs (tf32-rounded), masked = 0

// ---- helpers ----
__device__ __forceinline__ uint32_t f2tf(float x) {
    uint32_t y;
    asm("cvt.rna.tf32.f32 %0, %1;" : "=r"(y) : "f"(x));
    return y;
}
__device__ __forceinline__ float f2tf_f(float x) { return __uint_as_float(f2tf(x)); }
__device__ __forceinline__ int perm8(int x) { return 2 * (x & 3) + (x >> 2); } // x in 0..7
__device__ __forceinline__ void mma8(float c[4],
                                     uint32_t a0, uint32_t a1, uint32_t a2, uint32_t a3,
                                     uint32_t b0, uint32_t b1) {
    asm volatile("mma.sync.aligned.m16n8k8.row.col.f32.tf32.tf32.f32 "
                 "{%0,%1,%2,%3}, {%4,%5,%6,%7}, {%8,%9}, {%0,%1,%2,%3};\n"
                 : "+f"(c[0]), "+f"(c[1]), "+f"(c[2]), "+f"(c[3])
                 : "r"(a0), "r"(a1), "r"(a2), "r"(a3), "r"(b0), "r"(b1));
}
#define CP16(dst_u32, src_ptr) \
    asm volatile("cp.async.cg.shared.global [%0], [%1], 16;\n" :: "r"(dst_u32), "l"(src_ptr))
#define CP_COMMIT() asm volatile("cp.async.commit_group;\n")
#define CP_WAIT(n)  asm volatile("cp.async.wait_group %0;\n" :: "n"(n))

// ============================================================================
// x = tf32(input + pos_enc), stored with k-pair permutation. 8 elems/thread.
// ============================================================================
__global__ __launch_bounds__(256) void add_kernel(const float* __restrict__ a,
                                                  const float* __restrict__ b) {
    size_t i = ((size_t)blockIdx.x * 256 + threadIdx.x) * 8;
    float4 a0 = *(const float4*)(a + i),     a1 = *(const float4*)(a + i + 4);
    float4 b0 = *(const float4*)(b + i),     b1 = *(const float4*)(b + i + 4);
    float r0 = f2tf_f(a0.x + b0.x), r1 = f2tf_f(a0.y + b0.y);
    float r2 = f2tf_f(a0.z + b0.z), r3 = f2tf_f(a0.w + b0.w);
    float r4 = f2tf_f(a1.x + b1.x), r5 = f2tf_f(a1.y + b1.y);
    float r6 = f2tf_f(a1.z + b1.z), r7 = f2tf_f(a1.w + b1.w);
    float4 o0 = {r0, r4, r1, r5};
    float4 o1 = {r2, r6, r3, r7};
    *(float4*)(g_x + i) = o0;
    *(float4*)(g_x + i + 4) = o1;
}

// ============================================================================
// Transpose + round + k-permute weights:  dst[n][k'] = tf32(src[k][n])
// ============================================================================
template<int NCOLS>
__device__ __forceinline__ void transpose_round(const float* __restrict__ src,
                                                float* __restrict__ dst) {
    __shared__ float sm[32][33];
    const int t = threadIdx.x;
    const int k0 = blockIdx.y * 32, n0 = blockIdx.x * 32;
    {
        int kk = t >> 3, nn = (t & 7) * 4;
        float4 v = *(const float4*)(src + (size_t)(k0 + kk) * NCOLS + n0 + nn);
        sm[kk][nn] = v.x; sm[kk][nn + 1] = v.y; sm[kk][nn + 2] = v.z; sm[kk][nn + 3] = v.w;
    }
    __syncthreads();
    {
        int nrow = t >> 3;
        int q = t & 7, gg = q >> 1, h = q & 1;
        int o0 = h ? 2 : 0, o1 = h ? 6 : 4, o2 = h ? 3 : 1, o3 = h ? 7 : 5;
        int kb = gg * 8;
        float4 o;
        o.x = f2tf_f(sm[kb + o0][nrow]);
        o.y = f2tf_f(sm[kb + o1][nrow]);
        o.z = f2tf_f(sm[kb + o2][nrow]);
        o.w = f2tf_f(sm[kb + o3][nrow]);
        *(float4*)(dst + (size_t)(n0 + nrow) * 1024 + k0 + kb + h * 4) = o;
    }
}
__global__ __launch_bounds__(256) void round_wq(const float* __restrict__ src) {
    transpose_round<N3>(src, g_wqT);
}
__global__ __launch_bounds__(256) void round_wo(const float* __restrict__ src) {
    transpose_round<ND>(src, g_woT);
}

// ============================================================================
// tf32 GEMM body, cp.async 2-stage, LDS.64 pair fragments.
// ============================================================================
#define T_STG 5120   /* 128*40 floats per stage (A or B) */
#define NSTG  2
#define GEMM_SMEM (NSTG * 2 * T_STG * 4)   /* 81920 bytes */

struct GemmFrag { float acc[4][4][4]; };

__device__ __forceinline__ void gemm_issue(uint32_t aB, uint32_t bB, int s,
                                           const float* __restrict__ Ag,
                                           const float* __restrict__ Bg,
                                           int ldA, int ldB, int m0, int n0, int k0,
                                           int tx) {
#pragma unroll
    for (int p = 0; p < 4; p++) {
        int chunk = tx + p * 256;
        int row = chunk >> 3;
        int coff = (chunk & 7) * 4;
        CP16(aB + (uint32_t)(s * T_STG + row * 40 + coff) * 4u,
             Ag + (size_t)(m0 + row) * ldA + k0 + coff);
        CP16(bB + (uint32_t)(s * T_STG + row * 40 + coff) * 4u,
             Bg + (size_t)(n0 + row) * ldB + k0 + coff);
    }
}

__device__ __forceinline__ void gemm_compute(GemmFrag& F, const uint32_t* Asm,
                                             const uint32_t* Bsm, int s,
                                             int wm, int wn, int g, int tg) {
    const uint32_t* A = Asm + s * T_STG;
    const uint32_t* B = Bsm + s * T_STG;
#pragma unroll
    for (int ks = 0; ks < 32; ks += 8) {
        uint32_t a[4][4], b[4][2];
#pragma unroll
        for (int mi = 0; mi < 4; mi++) {
            int r = wm + mi * 16 + g;
            uint2 p0 = *(const uint2*)&A[r * 40 + ks + 2 * tg];
            uint2 p1 = *(const uint2*)&A[(r + 8) * 40 + ks + 2 * tg];
            a[mi][0] = p0.x; a[mi][2] = p0.y;
            a[mi][1] = p1.x; a[mi][3] = p1.y;
        }
#pragma unroll
        for (int ni = 0; ni < 4; ni++) {
            int c = wn + ni * 8 + g;
            uint2 pb = *(const uint2*)&B[c * 40 + ks + 2 * tg];
            b[ni][0] = pb.x; b[ni][1] = pb.y;
        }
#pragma unroll
        for (int mi = 0; mi < 4; mi++)
#pragma unroll
            for (int ni = 0; ni < 4; ni++)
                mma8(F.acc[mi][ni], a[mi][0], a[mi][1], a[mi][2], a[mi][3],
                     b[ni][0], b[ni][1]);
    }
}

#define GEMM_MAINLOOP(Ag, Bg, ldA, ldB)                                         \
    gemm_issue(aB, bB, 0, Ag, Bg, ldA, ldB, m0, n0, 0, tx);                     \
    CP_COMMIT();                                                                \
    { int buf = 0;                                                              \
    _Pragma("unroll 1")                                                         \
    for (int it = 0; it < 32; it++) {                                           \
        if (it + 1 < 32) {                                                      \
            gemm_issue(aB, bB, buf ^ 1, Ag, Bg, ldA, ldB, m0, n0,               \
                       (it + 1) * 32, tx);                                      \
            CP_COMMIT();                                                        \
            CP_WAIT(1);                                                         \
        } else {                                                                \
            CP_WAIT(0);                                                         \
        }                                                                       \
        __syncthreads();                                                        \
        gemm_compute(F, Asm, Bsm, buf, wm, wn, g, tg);                          \
        __syncthreads();                                                        \
        buf ^= 1;                                                               \
    } }

// ============================================================================
// QKV GEMM: [8192,3072] = g_x @ g_wqT^T; scatter rounded Q/K/V.
// ============================================================================
__global__ __launch_bounds__(256, 2) void qkv_gemm() {
    extern __shared__ float sm[];
    const uint32_t* Asm = (const uint32_t*)sm;
    const uint32_t* Bsm = (const uint32_t*)(sm + NSTG * T_STG);
    uint32_t aB = (uint32_t)__cvta_generic_to_shared(sm);
    uint32_t bB = (uint32_t)__cvta_generic_to_shared(sm + NSTG * T_STG);
    const int tx = threadIdx.x;
    const int warp = tx >> 5, lane = tx & 31;
    const int g = lane >> 2, tg = lane & 3;
    const int wm = (warp >> 2) * 64, wn = (warp & 3) * 32;
    const int m0 = blockIdx.y * 128, n0 = blockIdx.x * 128;

    GemmFrag F;
#pragma unroll
    for (int mi = 0; mi < 4; mi++)
#pragma unroll
        for (int ni = 0; ni < 4; ni++)
#pragma unroll
            for (int r = 0; r < 4; r++) F.acc[mi][ni][r] = 0.f;

    GEMM_MAINLOOP(g_x, g_wqT, Dq, Dq)

#pragma unroll
    for (int mi = 0; mi < 4; mi++)
#pragma unroll
        for (int ni = 0; ni < 4; ni++)
#pragma unroll
            for (int rr = 0; rr < 2; rr++) {
                int row = m0 + wm + mi * 16 + g + rr * 8;
                int b = row & 7, t = row >> 3;
#pragma unroll
                for (int cc = 0; cc < 2; cc++) {
                    int col = n0 + wn + ni * 8 + 2 * tg + cc;
                    int part = col >> 10;
                    int rem = col & 1023;
                    int n = rem >> 6, d = rem & 63;
                    float val = f2tf_f(F.acc[mi][ni][rr * 2 + cc]);
                    size_t base = ((size_t)((b << 4) + n) * Tq + t) * DH;
                    if (part == 0)       g_q[base + (d & ~7) + perm8(d & 7)] = val;
                    else if (part == 1)  g_k[base + (d & ~7) + perm8(d & 7)] = val;
                    else                 g_v[base + d] = val;
                }
            }
}

// ============================================================================
// Output projection: out[8192,1024] = g_av @ g_woT^T, STG.64 epilogue.
// ============================================================================
__global__ __launch_bounds__(256, 2) void out_gemm(float* __restrict__ out) {
    extern __shared__ float sm[];
    const uint32_t* Asm = (const uint32_t*)sm;
    const uint32_t* Bsm = (const uint32_t*)(sm + NSTG * T_STG);
    uint32_t aB = (uint32_t)__cvta_generic_to_shared(sm);
    uint32_t bB = (uint32_t)__cvta_generic_to_shared(sm + NSTG * T_STG);
    const int tx = threadIdx.x;
    const int warp = tx >> 5, lane = tx & 31;
    const int g = lane >> 2, tg = lane & 3;
    const int wm = (warp >> 2) * 64, wn = (warp & 3) * 32;
    const int m0 = blockIdx.y * 128, n0 = blockIdx.x * 128;

    GemmFrag F;
#pragma unroll
    for (int mi = 0; mi < 4; mi++)
#pragma unroll
        for (int ni = 0; ni < 4; ni++)
#pragma unroll
            for (int r = 0; r < 4; r++) F.acc[mi][ni][r] = 0.f;

    GEMM_MAINLOOP(g_av, g_woT, ND, ND)

#pragma unroll
    for (int mi = 0; mi < 4; mi++)
#pragma unroll
        for (int ni = 0; ni < 4; ni++)
#pragma unroll
            for (int rr = 0; rr < 2; rr++) {
                int row = m0 + wm + mi * 16 + g + rr * 8;
                int col = n0 + wn + ni * 8 + 2 * tg;
                float2 v = { F.acc[mi][ni][rr * 2], F.acc[mi][ni][rr * 2 + 1] };
                *(float2*)(out + (size_t)row * ND + col) = v;
            }
}

// ============================================================================
// Scores: CTA per (z, 64-row i-tile). Q persistent, K-tiles 2-stage cp.async.
// (R12-identical)
// ============================================================================
#define SCT (64*72)
#define SC_SMEM (3 * SCT * 4)   /* 55296 bytes */

__global__ __launch_bounds__(256, 3) void score_kernel() {
    extern __shared__ float sm[];
    uint32_t* Qs = (uint32_t*)sm;            // [64][72]
    float* Kf = sm + SCT;                    // 2 stages of [64][72]
    uint32_t kB = (uint32_t)__cvta_generic_to_shared(Kf);

    const int ti = (Tq / 64 - 1) - blockIdx.x;   // heavy tiles first
    const int z = blockIdx.y;
    const int tx = threadIdx.x;
    const int warp = tx >> 5, lane = tx & 31;
    const int g = lane >> 2, tg = lane & 3;
    const int wm = (warp >> 2) * 32;
    const int wn = (warp & 3) * 16;

    const int lrow = tx >> 2, lcol = (tx & 3) * 16;
    const float* kbase = g_k + ((size_t)z * Tq + lrow) * DH + lcol;

    const int nj = ti + 1;

    // prologue: K stage 0 <- tj 0
#pragma unroll
    for (int q = 0; q < 4; q++)
        CP16(kB + (uint32_t)(lrow * 72 + lcol + q * 4) * 4u, kbase + q * 4);
    CP_COMMIT();

    // persistent Q tile (pre-rounded, d-permuted -> raw uint4 copies)
    {
        const float* qb = g_q + ((size_t)z * Tq + ti * 64) * DH;
        const int lr = tx >> 2, lc0 = (tx & 3) << 2;
#pragma unroll
        for (int rr = 0; rr < 4; rr++) {
            int c = lc0 + rr * 16;
            *(uint4*)&Qs[lr * 72 + c] = *(const uint4*)(qb + lr * DH + c);
        }
    }

    int buf = 0;
#pragma unroll 1
    for (int tj = 0; tj < nj; tj++) {
        if (tj + 1 < nj) {
            int s = buf ^ 1;
#pragma unroll
            for (int q = 0; q < 4; q++)
                CP16(kB + (uint32_t)(s * SCT + lrow * 72 + lcol + q * 4) * 4u,
                     kbase + (size_t)(tj + 1) * 64 * DH + q * 4);
            CP_COMMIT();
            CP_WAIT(1);
        } else {
            CP_WAIT(0);
        }
        __syncthreads();

        const uint32_t* K = (const uint32_t*)(Kf + buf * SCT);

        float acc[2][2][4];
#pragma unroll
        for (int mi = 0; mi < 2; mi++)
#pragma unroll
            for (int ni = 0; ni < 2; ni++)
#pragma unroll
                for (int r = 0; r < 4; r++) acc[mi][ni][r] = 0.f;

#pragma unroll
        for (int ks = 0; ks < 64; ks += 8) {
            uint32_t a[2][4], b[2][2];
#pragma unroll
            for (int mi = 0; mi < 2; mi++) {
                int r = wm + mi * 16 + g;
                uint2 p0 = *(const uint2*)&Qs[r * 72 + ks + 2 * tg];
                uint2 p1 = *(const uint2*)&Qs[(r + 8) * 72 + ks + 2 * tg];
                a[mi][0] = p0.x; a[mi][2] = p0.y;
                a[mi][1] = p1.x; a[mi][3] = p1.y;
            }
#pragma unroll
            for (int ni = 0; ni < 2; ni++) {
                int c = wn + ni * 8 + g;
                uint2 pb = *(const uint2*)&K[c * 72 + ks + 2 * tg];
                b[ni][0] = pb.x; b[ni][1] = pb.y;
            }
#pragma unroll
            for (int mi = 0; mi < 2; mi++)
#pragma unroll
                for (int ni = 0; ni < 2; ni++)
                    mma8(acc[mi][ni], a[mi][0], a[mi][1], a[mi][2], a[mi][3],
                         b[ni][0], b[ni][1]);
        }

        const float scale = 0.125f;
        if (tj < ti) {
            // fully unmasked tile: STG.64 pair stores
#pragma unroll
            for (int mi = 0; mi < 2; mi++)
#pragma unroll
                for (int ni = 0; ni < 2; ni++)
#pragma unroll
                    for (int rr = 0; rr < 2; rr++) {
                        int i = ti * 64 + wm + mi * 16 + g + rr * 8;
                        int j = tj * 64 + wn + ni * 8 + 2 * tg;
                        float2 v = { acc[mi][ni][rr * 2] * scale,
                                     acc[mi][ni][rr * 2 + 1] * scale };
                        *(float2*)(g_S + ((size_t)z * Tq + i) * Tq + j) = v;
                    }
        } else {
            // diagonal tile: predicated scalar stores (keep masked region zero)
#pragma unroll
            for (int mi = 0; mi < 2; mi++)
#pragma unroll
                for (int ni = 0; ni < 2; ni++)
#pragma unroll
                    for (int rr = 0; rr < 2; rr++) {
                        int i = ti * 64 + wm + mi * 16 + g + rr * 8;
#pragma unroll
                        for (int cc = 0; cc < 2; cc++) {
                            int j = tj * 64 + wn + ni * 8 + 2 * tg + cc;
                            if (j <= i)
                                g_S[((size_t)z * Tq + i) * Tq + j] =
                                    acc[mi][ni][rr * 2 + cc] * scale;
                        }
                    }
        }
        __syncthreads();
        buf ^= 1;
    }
}

// ============================================================================
// Row softmax, vectorized + len-aware, writes tf32-rounded probs.
// (R12-identical)
// ============================================================================
__global__ __launch_bounds__(128) void softmax_kernel() {
    const int rid = blockIdx.x;
    const int i = rid & (Tq - 1);
    float* row = g_S + (size_t)rid * Tq;
    const int len = i + 1;
    const int tx = threadIdx.x;
    const int j0 = tx * 8;

    float vals[8];
    if (j0 < len) {
        float4 v0 = *(const float4*)(row + j0);
        float4 v1 = *(const float4*)(row + j0 + 4);
        vals[0] = v0.x; vals[1] = v0.y; vals[2] = v0.z; vals[3] = v0.w;
        vals[4] = v1.x; vals[5] = v1.y; vals[6] = v1.z; vals[7] = v1.w;
    } else {
#pragma unroll
        for (int u = 0; u < 8; u++) vals[u] = -1e30f;
    }

    float m = -1e30f;
#pragma unroll
    for (int u = 0; u < 8; u++)
        if (j0 + u < len) m = fmaxf(m, vals[u]);

    __shared__ float redm[4];
    __shared__ float reds[4];
#pragma unroll
    for (int o = 16; o; o >>= 1) m = fmaxf(m, __shfl_xor_sync(0xffffffffu, m, o));
    if ((tx & 31) == 0) redm[tx >> 5] = m;
    __syncthreads();
    m = fmaxf(fmaxf(redm[0], redm[1]), fmaxf(redm[2], redm[3]));

    float s = 0.f;
#pragma unroll
    for (int u = 0; u < 8; u++) {
        float e = __expf(vals[u] - m);
        vals[u] = e;
        if (j0 + u < len) s += e;
    }
#pragma unroll
    for (int o = 16; o; o >>= 1) s += __shfl_xor_sync(0xffffffffu, s, o);
    if ((tx & 31) == 0) reds[tx >> 5] = s;
    __syncthreads();
    s = reds[0] + reds[1] + reds[2] + reds[3];
    const float inv = 1.0f / s;

    if (j0 + 8 <= len) {
        float4 o0, o1;
        o0.x = f2tf_f(vals[0] * inv); o0.y = f2tf_f(vals[1] * inv);
        o0.z = f2tf_f(vals[2] * inv); o0.w = f2tf_f(vals[3] * inv);
        o1.x = f2tf_f(vals[4] * inv); o1.y = f2tf_f(vals[5] * inv);
        o1.z = f2tf_f(vals[6] * inv); o1.w = f2tf_f(vals[7] * inv);
        *(float4*)(row + j0) = o0;
        *(float4*)(row + j0 + 4) = o1;
    } else if (j0 < len) {
#pragma unroll
        for (int u = 0; u < 8; u++)
            if (j0 + u < len) row[j0 + u] = f2tf_f(vals[u] * inv);
    }
}

// ============================================================================
// Coverage: out[b][j][i] = mean_n prob[b][n][i][j]. (unchanged)
// ============================================================================
__global__ __launch_bounds__(256) void coverage_kernel(float* __restrict__ out_cov) {
    const int b = blockIdx.z;
    const int i0 = blockIdx.y * 32, j0 = blockIdx.x * 32;
    const int tx = threadIdx.x;

    if (j0 >= i0 + 32) {
#pragma unroll
        for (int it = 0; it < 4; it++) {
            int idx = tx + it * 256;
            int jj = idx >> 5, ii = idx & 31;
            out_cov[((size_t)b * Tq + j0 + jj) * Tq + i0 + ii] = 0.f;
        }
        return;
    }

    __shared__ float cs[32][33];
#pragma unroll
    for (int it = 0; it < 4; it++) {
        int idx = tx + it * 256;
        int ii = idx >> 5, jj = idx & 31;
        float s = 0.f;
#pragma unroll
        for (int n = 0; n < 16; n++)
            s += g_S[(((size_t)(b * 16 + n) * Tq + i0 + ii) * Tq) + j0 + jj];
        cs[ii][jj] = s * (1.0f / 16.0f);
    }
    __syncthreads();
#pragma unroll
    for (int it = 0; it < 4; it++) {
        int idx = tx + it * 256;
        int jj = idx >> 5, ii = idx & 31;
        out_cov[((size_t)b * Tq + j0 + jj) * Tq + i0 + ii] = cs[ii][jj];
    }
}

// ============================================================================
// PV: attn_vec = P @ V, cp.async 2-stage, cvt-free mainloop.
// ONLY change vs R12: __launch_bounds__(256, 3) — 3 CTAs/SM (215KB smem fits).
// ============================================================================
#define AVP 4352   /* 64*68 floats per stage */
#define AVV 4608   /* 64*72 floats per stage */
#define AV_SMEM ((2*AVP + 2*AVV) * 4)   /* 71680 bytes */

__global__ __launch_bounds__(256, 3) void av_kernel() {
    extern __shared__ float sm[];
    float* Pf = sm;
    float* Vf = sm + 2 * AVP;
    uint32_t pB = (uint32_t)__cvta_generic_to_shared(Pf);
    uint32_t vB = (uint32_t)__cvta_generic_to_shared(Vf);

    const int ti = (Tq / 64 - 1) - blockIdx.x;   // heavy tiles first
    const int z = blockIdx.y;
    const int bq = z >> 4, nh = z & 15;
    const int tx = threadIdx.x;
    const int warp = tx >> 5, lane = tx & 31;
    const int g = lane >> 2, tg = lane & 3;
    const int wm = (warp >> 2) * 32;
    const int wn = (warp & 3) * 16;

    const int lrow = tx >> 2, lcol = (tx & 3) * 16;
    const float* pbase = g_S + ((size_t)z * Tq + ti * 64 + lrow) * Tq + lcol;
    const float* vbase = g_v + ((size_t)z * Tq + lrow) * DH + lcol;

    const int nj = ti + 1;

    float acc[2][2][4];
#pragma unroll
    for (int mi = 0; mi < 2; mi++)
#pragma unroll
        for (int ni = 0; ni < 2; ni++)
#pragma unroll
            for (int r = 0; r < 4; r++) acc[mi][ni][r] = 0.f;

#pragma unroll
    for (int q = 0; q < 4; q++) {
        CP16(pB + (uint32_t)(lrow * 68 + lcol + q * 4) * 4u, pbase + q * 4);
        CP16(vB + (uint32_t)(lrow * 72 + lcol + q * 4) * 4u, vbase + q * 4);
    }
    CP_COMMIT();

    int buf = 0;
#pragma unroll 1
    for (int jt = 0; jt < nj; jt++) {
        if (jt + 1 < nj) {
            int s = buf ^ 1;
            int jn = jt + 1;
#pragma unroll
            for (int q = 0; q < 4; q++) {
                CP16(pB + (uint32_t)(s * AVP + lrow * 68 + lcol + q * 4) * 4u,
                     pbase + jn * 64 + q * 4);
                CP16(vB + (uint32_t)(s * AVV + lrow * 72 + lcol + q * 4) * 4u,
                     vbase + (size_t)jn * 64 * DH + q * 4);
            }
            CP_COMMIT();
            CP_WAIT(1);
        } else {
            CP_WAIT(0);
        }
        __syncthreads();

        const uint32_t* P = (const uint32_t*)(Pf + buf * AVP);
        const uint32_t* V = (const uint32_t*)(Vf + buf * AVV);
#pragma unroll
        for (int ks = 0; ks < 64; ks += 8) {
            uint32_t a[2][4], b[2][2];
#pragma unroll
            for (int mi = 0; mi < 2; mi++) {
                int r = wm + mi * 16 + g;
                a[mi][0] = P[r * 68 + ks + tg];
                a[mi][1] = P[(r + 8) * 68 + ks + tg];
                a[mi][2] = P[r * 68 + ks + tg + 4];
                a[mi][3] = P[(r + 8) * 68 + ks + tg + 4];
            }
#pragma unroll
            for (int ni = 0; ni < 2; ni++) {
                int c = wn + ni * 8 + g;
                b[ni][0] = V[(ks + tg) * 72 + c];
                b[ni][1] = V[(ks + tg + 4) * 72 + c];
            }
#pragma unroll
            for (int mi = 0; mi < 2; mi++)
#pragma unroll
                for (int ni = 0; ni < 2; ni++)
                    mma8(acc[mi][ni], a[mi][0], a[mi][1], a[mi][2], a[mi][3],
                         b[ni][0], b[ni][1]);
        }
        __syncthreads();
        buf ^= 1;
    }

#pragma unroll
    for (int mi = 0; mi < 2; mi++)
#pragma unroll
        for (int ni = 0; ni < 2; ni++)
#pragma unroll
            for (int rr = 0; rr < 2; rr++) {
                int i = ti * 64 + wm + mi * 16 + g + rr * 8;
#pragma unroll
                for (int cc = 0; cc < 2; cc++) {
                    int d = wn + ni * 8 + 2 * tg + cc;
                    int dp = (d & ~7) + perm8(d & 7);
                    g_av[((size_t)(i * Bq + bq)) * ND + nh * 64 + dp] = acc[mi][ni][rr * 2 + cc];
                }
            }
}

// ============================================================================
extern "C" void kernel_launch(void* const* d_in, const int* in_sizes, int n_in,
                              void* d_out, int out_size) {
    const float* inp  = (const float*)d_in[0];
    const float* pe   = (const float*)d_in[1];
    const float* Wqkv = (const float*)d_in[3];
    const float* Wo   = (const float*)d_in[4];

    float* out_attn = (float*)d_out;
    float* out_cov  = out_attn + (size_t)TB * ND;

    cudaFuncSetAttribute(qkv_gemm, cudaFuncAttributeMaxDynamicSharedMemorySize, GEMM_SMEM);
    cudaFuncSetAttribute(out_gemm, cudaFuncAttributeMaxDynamicSharedMemorySize, GEMM_SMEM);
    cudaFuncSetAttribute(av_kernel, cudaFuncAttributeMaxDynamicSharedMemorySize, AV_SMEM);
    cudaFuncSetAttribute(score_kernel, cudaFuncAttributeMaxDynamicSharedMemorySize, SC_SMEM);

    add_kernel<<<TB * Dq / 2048, 256>>>(inp, pe);
    round_wq<<<dim3(N3 / 32, Dq / 32), 256>>>(Wqkv);
    round_wo<<<dim3(ND / 32, ND / 32), 256>>>(Wo);
    qkv_gemm<<<dim3(N3 / 128, TB / 128), 256, GEMM_SMEM>>>();
    score_kernel<<<dim3(Tq / 64, ZN), 256, SC_SMEM>>>();
    softmax_kernel<<<ZN * Tq, 128>>>();
    coverage_kernel<<<dim3(Tq / 32, Tq / 32, Bq), 256>>>(out_cov);
    av_kernel<<<dim3(Tq / 64, ZN), 256, AV_SMEM>>>();
    out_gemm<<<dim3(ND / 128, TB / 128), 256, GEMM_SMEM>>>(out_attn);
}

// round 17
// speedup vs baseline: 1.1341x; 1.1187x over previous
#include <cuda_runtime.h>
#include <cuda_fp16.h>
#include <stdint.h>
#include <string.h>
#include <math.h>

#define Tq 1024
#define Bq 8
#define Dq 1024
#define NH 16
#define DH 64
#define TB (Tq*Bq)       /* 8192 rows */
#define ND (NH*DH)       /* 1024 */
#define N3 (3*ND)        /* 3072 */
#define ZN (Bq*NH)       /* 128 */

// ---- static scratch (zero-initialized) ----
__device__ float g_x[(size_t)TB*Dq];        // rounded x, k-permuted
__device__ float g_wqT[(size_t)N3*Dq];      // rounded W_qkv^T [n][k], k-permuted
__device__ float g_woT[(size_t)ND*ND];      // rounded W_o^T  [n][k], k-permuted
__device__ float g_q[(size_t)ZN*Tq*DH];     // rounded, [b][n][t][d], d-permuted
__device__ float g_k[(size_t)ZN*Tq*DH];     // rounded, d-permuted
__device__ float g_v[(size_t)ZN*Tq*DH];     // rounded, natural d
__device__ float g_av[(size_t)TB*ND];       // [t*B+b][col], col-permuted
__device__ float g_S[(size_t)ZN*Tq*Tq];     // fp32 SCORES (masked region unused)
__device__ __half g_P[(size_t)ZN*Tq*Tq];    // fp16 probs, col pair-PERMUTED, masked = 0

// ---- helpers ----
__device__ __forceinline__ uint32_t f2tf(float x) {
    uint32_t y;
    asm("cvt.rna.tf32.f32 %0, %1;" : "=r"(y) : "f"(x));
    return y;
}
__device__ __forceinline__ float f2tf_f(float x) { return __uint_as_float(f2tf(x)); }
__device__ __forceinline__ int perm8(int x) { return 2 * (x & 3) + (x >> 2); } // 0..7
__device__ __forceinline__ uint32_t h2u(__half2 h) {
    uint32_t u;
    memcpy(&u, &h, 4);
    return u;
}
__device__ __forceinline__ void mma8(float c[4],
                                     uint32_t a0, uint32_t a1, uint32_t a2, uint32_t a3,
                                     uint32_t b0, uint32_t b1) {
    asm volatile("mma.sync.aligned.m16n8k8.row.col.f32.tf32.tf32.f32 "
                 "{%0,%1,%2,%3}, {%4,%5,%6,%7}, {%8,%9}, {%0,%1,%2,%3};\n"
                 : "+f"(c[0]), "+f"(c[1]), "+f"(c[2]), "+f"(c[3])
                 : "r"(a0), "r"(a1), "r"(a2), "r"(a3), "r"(b0), "r"(b1));
}
#define CP16(dst_u32, src_ptr) \
    asm volatile("cp.async.cg.shared.global [%0], [%1], 16;\n" :: "r"(dst_u32), "l"(src_ptr))
#define CP_COMMIT() asm volatile("cp.async.commit_group;\n")
#define CP_WAIT(n)  asm volatile("cp.async.wait_group %0;\n" :: "n"(n))

// ============================================================================
// x = tf32(input + pos_enc), stored with k-pair permutation.
// ============================================================================
__global__ __launch_bounds__(256) void add_kernel(const float* __restrict__ a,
                                                  const float* __restrict__ b) {
    size_t i = ((size_t)blockIdx.x * 256 + threadIdx.x) * 8;
    float4 a0 = *(const float4*)(a + i),     a1 = *(const float4*)(a + i + 4);
    float4 b0 = *(const float4*)(b + i),     b1 = *(const float4*)(b + i + 4);
    float r0 = f2tf_f(a0.x + b0.x), r1 = f2tf_f(a0.y + b0.y);
    float r2 = f2tf_f(a0.z + b0.z), r3 = f2tf_f(a0.w + b0.w);
    float r4 = f2tf_f(a1.x + b1.x), r5 = f2tf_f(a1.y + b1.y);
    float r6 = f2tf_f(a1.z + b1.z), r7 = f2tf_f(a1.w + b1.w);
    float4 o0 = {r0, r4, r1, r5};
    float4 o1 = {r2, r6, r3, r7};
    *(float4*)(g_x + i) = o0;
    *(float4*)(g_x + i + 4) = o1;
}

// ============================================================================
// Transpose + round + k-permute weights.
// ============================================================================
template<int NCOLS>
__device__ __forceinline__ void transpose_round(const float* __restrict__ src,
                                                float* __restrict__ dst) {
    __shared__ float sm[32][33];
    const int t = threadIdx.x;
    const int k0 = blockIdx.y * 32, n0 = blockIdx.x * 32;
    {
        int kk = t >> 3, nn = (t & 7) * 4;
        float4 v = *(const float4*)(src + (size_t)(k0 + kk) * NCOLS + n0 + nn);
        sm[kk][nn] = v.x; sm[kk][nn + 1] = v.y; sm[kk][nn + 2] = v.z; sm[kk][nn + 3] = v.w;
    }
    __syncthreads();
    {
        int nrow = t >> 3;
        int q = t & 7, gg = q >> 1, h = q & 1;
        int o0 = h ? 2 : 0, o1 = h ? 6 : 4, o2 = h ? 3 : 1, o3 = h ? 7 : 5;
        int kb = gg * 8;
        float4 o;
        o.x = f2tf_f(sm[kb + o0][nrow]);
        o.y = f2tf_f(sm[kb + o1][nrow]);
        o.z = f2tf_f(sm[kb + o2][nrow]);
        o.w = f2tf_f(sm[kb + o3][nrow]);
        *(float4*)(dst + (size_t)(n0 + nrow) * 1024 + k0 + kb + h * 4) = o;
    }
}
__global__ __launch_bounds__(256) void round_wq(const float* __restrict__ src) {
    transpose_round<N3>(src, g_wqT);
}
__global__ __launch_bounds__(256) void round_wo(const float* __restrict__ src) {
    transpose_round<ND>(src, g_woT);
}

// ============================================================================
// tf32 GEMM body, cp.async 2-stage, LDS.64 pair fragments.
// ============================================================================
#define T_STG 5120
#define NSTG  2
#define GEMM_SMEM (NSTG * 2 * T_STG * 4)

struct GemmFrag { float acc[4][4][4]; };

__device__ __forceinline__ void gemm_issue(uint32_t aB, uint32_t bB, int s,
                                           const float* __restrict__ Ag,
                                           const float* __restrict__ Bg,
                                           int ldA, int ldB, int m0, int n0, int k0,
                                           int tx) {
#pragma unroll
    for (int p = 0; p < 4; p++) {
        int chunk = tx + p * 256;
        int row = chunk >> 3;
        int coff = (chunk & 7) * 4;
        CP16(aB + (uint32_t)(s * T_STG + row * 40 + coff) * 4u,
             Ag + (size_t)(m0 + row) * ldA + k0 + coff);
        CP16(bB + (uint32_t)(s * T_STG + row * 40 + coff) * 4u,
             Bg + (size_t)(n0 + row) * ldB + k0 + coff);
    }
}

__device__ __forceinline__ void gemm_compute(GemmFrag& F, const uint32_t* Asm,
                                             const uint32_t* Bsm, int s,
                                             int wm, int wn, int g, int tg) {
    const uint32_t* A = Asm + s * T_STG;
    const uint32_t* B = Bsm + s * T_STG;
#pragma unroll
    for (int ks = 0; ks < 32; ks += 8) {
        uint32_t a[4][4], b[4][2];
#pragma unroll
        for (int mi = 0; mi < 4; mi++) {
            int r = wm + mi * 16 + g;
            uint2 p0 = *(const uint2*)&A[r * 40 + ks + 2 * tg];
            uint2 p1 = *(const uint2*)&A[(r + 8) * 40 + ks + 2 * tg];
            a[mi][0] = p0.x; a[mi][2] = p0.y;
            a[mi][1] = p1.x; a[mi][3] = p1.y;
        }
#pragma unroll
        for (int ni = 0; ni < 4; ni++) {
            int c = wn + ni * 8 + g;
            uint2 pb = *(const uint2*)&B[c * 40 + ks + 2 * tg];
            b[ni][0] = pb.x; b[ni][1] = pb.y;
        }
#pragma unroll
        for (int mi = 0; mi < 4; mi++)
#pragma unroll
            for (int ni = 0; ni < 4; ni++)
                mma8(F.acc[mi][ni], a[mi][0], a[mi][1], a[mi][2], a[mi][3],
                     b[ni][0], b[ni][1]);
    }
}

#define GEMM_MAINLOOP(Ag, Bg, ldA, ldB)                                         \
    gemm_issue(aB, bB, 0, Ag, Bg, ldA, ldB, m0, n0, 0, tx);                     \
    CP_COMMIT();                                                                \
    { int buf = 0;                                                              \
    _Pragma("unroll 1")                                                         \
    for (int it = 0; it < 32; it++) {                                           \
        if (it + 1 < 32) {                                                      \
            gemm_issue(aB, bB, buf ^ 1, Ag, Bg, ldA, ldB, m0, n0,               \
                       (it + 1) * 32, tx);                                      \
            CP_COMMIT();                                                        \
            CP_WAIT(1);                                                         \
        } else {                                                                \
            CP_WAIT(0);                                                         \
        }                                                                       \
        __syncthreads();                                                        \
        gemm_compute(F, Asm, Bsm, buf, wm, wn, g, tg);                          \
        __syncthreads();                                                        \
        buf ^= 1;                                                               \
    } }

// ============================================================================
// QKV GEMM.
// ============================================================================
__global__ __launch_bounds__(256, 2) void qkv_gemm() {
    extern __shared__ float sm[];
    const uint32_t* Asm = (const uint32_t*)sm;
    const uint32_t* Bsm = (const uint32_t*)(sm + NSTG * T_STG);
    uint32_t aB = (uint32_t)__cvta_generic_to_shared(sm);
    uint32_t bB = (uint32_t)__cvta_generic_to_shared(sm + NSTG * T_STG);
    const int tx = threadIdx.x;
    const int warp = tx >> 5, lane = tx & 31;
    const int g = lane >> 2, tg = lane & 3;
    const int wm = (warp >> 2) * 64, wn = (warp & 3) * 32;
    const int m0 = blockIdx.y * 128, n0 = blockIdx.x * 128;

    GemmFrag F;
#pragma unroll
    for (int mi = 0; mi < 4; mi++)
#pragma unroll
        for (int ni = 0; ni < 4; ni++)
#pragma unroll
            for (int r = 0; r < 4; r++) F.acc[mi][ni][r] = 0.f;

    GEMM_MAINLOOP(g_x, g_wqT, Dq, Dq)

#pragma unroll
    for (int mi = 0; mi < 4; mi++)
#pragma unroll
        for (int ni = 0; ni < 4; ni++)
#pragma unroll
            for (int rr = 0; rr < 2; rr++) {
                int row = m0 + wm + mi * 16 + g + rr * 8;
                int b = row & 7, t = row >> 3;
#pragma unroll
                for (int cc = 0; cc < 2; cc++) {
                    int col = n0 + wn + ni * 8 + 2 * tg + cc;
                    int part = col >> 10;
                    int rem = col & 1023;
                    int n = rem >> 6, d = rem & 63;
                    float val = f2tf_f(F.acc[mi][ni][rr * 2 + cc]);
                    size_t base = ((size_t)((b << 4) + n) * Tq + t) * DH;
                    if (part == 0)       g_q[base + (d & ~7) + perm8(d & 7)] = val;
                    else if (part == 1)  g_k[base + (d & ~7) + perm8(d & 7)] = val;
                    else                 g_v[base + d] = val;
                }
            }
}

// ============================================================================
// Output projection.
// ============================================================================
__global__ __launch_bounds__(256, 2) void out_gemm(float* __restrict__ out) {
    extern __shared__ float sm[];
    const uint32_t* Asm = (const uint32_t*)sm;
    const uint32_t* Bsm = (const uint32_t*)(sm + NSTG * T_STG);
    uint32_t aB = (uint32_t)__cvta_generic_to_shared(sm);
    uint32_t bB = (uint32_t)__cvta_generic_to_shared(sm + NSTG * T_STG);
    const int tx = threadIdx.x;
    const int warp = tx >> 5, lane = tx & 31;
    const int g = lane >> 2, tg = lane & 3;
    const int wm = (warp >> 2) * 64, wn = (warp & 3) * 32;
    const int m0 = blockIdx.y * 128, n0 = blockIdx.x * 128;

    GemmFrag F;
#pragma unroll
    for (int mi = 0; mi < 4; mi++)
#pragma unroll
        for (int ni = 0; ni < 4; ni++)
#pragma unroll
            for (int r = 0; r < 4; r++) F.acc[mi][ni][r] = 0.f;

    GEMM_MAINLOOP(g_av, g_woT, ND, ND)

#pragma unroll
    for (int mi = 0; mi < 4; mi++)
#pragma unroll
        for (int ni = 0; ni < 4; ni++)
#pragma unroll
            for (int rr = 0; rr < 2; rr++) {
                int row = m0 + wm + mi * 16 + g + rr * 8;
                int col = n0 + wn + ni * 8 + 2 * tg;
                float2 v = { F.acc[mi][ni][rr * 2], F.acc[mi][ni][rr * 2 + 1] };
                *(float2*)(out + (size_t)row * ND + col) = v;
            }
}

// ============================================================================
// Scores: CTA per (z, 64-row i-tile). (R14-identical)
// ============================================================================
#define SCT (64*72)
#define SC_SMEM (3 * SCT * 4)

__global__ __launch_bounds__(256, 3) void score_kernel() {
    extern __shared__ float sm[];
    uint32_t* Qs = (uint32_t*)sm;
    float* Kf = sm + SCT;
    uint32_t kB = (uint32_t)__cvta_generic_to_shared(Kf);

    const int ti = (Tq / 64 - 1) - blockIdx.x;
    const int z = blockIdx.y;
    const int tx = threadIdx.x;
    const int warp = tx >> 5, lane = tx & 31;
    const int g = lane >> 2, tg = lane & 3;
    const int wm = (warp >> 2) * 32;
    const int wn = (warp & 3) * 16;

    const int lrow = tx >> 2, lcol = (tx & 3) * 16;
    const float* kbase = g_k + ((size_t)z * Tq + lrow) * DH + lcol;

    const int nj = ti + 1;

#pragma unroll
    for (int q = 0; q < 4; q++)
        CP16(kB + (uint32_t)(lrow * 72 + lcol + q * 4) * 4u, kbase + q * 4);
    CP_COMMIT();

    {
        const float* qb = g_q + ((size_t)z * Tq + ti * 64) * DH;
        const int lr = tx >> 2, lc0 = (tx & 3) << 2;
#pragma unroll
        for (int rr = 0; rr < 4; rr++) {
            int c = lc0 + rr * 16;
            *(uint4*)&Qs[lr * 72 + c] = *(const uint4*)(qb + lr * DH + c);
        }
    }

    int buf = 0;
#pragma unroll 1
    for (int tj = 0; tj < nj; tj++) {
        if (tj + 1 < nj) {
            int s = buf ^ 1;
#pragma unroll
            for (int q = 0; q < 4; q++)
                CP16(kB + (uint32_t)(s * SCT + lrow * 72 + lcol + q * 4) * 4u,
                     kbase + (size_t)(tj + 1) * 64 * DH + q * 4);
            CP_COMMIT();
            CP_WAIT(1);
        } else {
            CP_WAIT(0);
        }
        __syncthreads();

        const uint32_t* K = (const uint32_t*)(Kf + buf * SCT);

        float acc[2][2][4];
#pragma unroll
        for (int mi = 0; mi < 2; mi++)
#pragma unroll
            for (int ni = 0; ni < 2; ni++)
#pragma unroll
                for (int r = 0; r < 4; r++) acc[mi][ni][r] = 0.f;

#pragma unroll
        for (int ks = 0; ks < 64; ks += 8) {
            uint32_t a[2][4], b[2][2];
#pragma unroll
            for (int mi = 0; mi < 2; mi++) {
                int r = wm + mi * 16 + g;
                uint2 p0 = *(const uint2*)&Qs[r * 72 + ks + 2 * tg];
                uint2 p1 = *(const uint2*)&Qs[(r + 8) * 72 + ks + 2 * tg];
                a[mi][0] = p0.x; a[mi][2] = p0.y;
                a[mi][1] = p1.x; a[mi][3] = p1.y;
            }
#pragma unroll
            for (int ni = 0; ni < 2; ni++) {
                int c = wn + ni * 8 + g;
                uint2 pb = *(const uint2*)&K[c * 72 + ks + 2 * tg];
                b[ni][0] = pb.x; b[ni][1] = pb.y;
            }
#pragma unroll
            for (int mi = 0; mi < 2; mi++)
#pragma unroll
                for (int ni = 0; ni < 2; ni++)
                    mma8(acc[mi][ni], a[mi][0], a[mi][1], a[mi][2], a[mi][3],
                         b[ni][0], b[ni][1]);
        }

        const float scale = 0.125f;
        if (tj < ti) {
#pragma unroll
            for (int mi = 0; mi < 2; mi++)
#pragma unroll
                for (int ni = 0; ni < 2; ni++)
#pragma unroll
                    for (int rr = 0; rr < 2; rr++) {
                        int i = ti * 64 + wm + mi * 16 + g + rr * 8;
                        int j = tj * 64 + wn + ni * 8 + 2 * tg;
                        float2 v = { acc[mi][ni][rr * 2] * scale,
                                     acc[mi][ni][rr * 2 + 1] * scale };
                        *(float2*)(g_S + ((size_t)z * Tq + i) * Tq + j) = v;
                    }
        } else {
#pragma unroll
            for (int mi = 0; mi < 2; mi++)
#pragma unroll
                for (int ni = 0; ni < 2; ni++)
#pragma unroll
                    for (int rr = 0; rr < 2; rr++) {
                        int i = ti * 64 + wm + mi * 16 + g + rr * 8;
#pragma unroll
                        for (int cc = 0; cc < 2; cc++) {
                            int j = tj * 64 + wn + ni * 8 + 2 * tg + cc;
                            if (j <= i)
                                g_S[((size_t)z * Tq + i) * Tq + j] =
                                    acc[mi][ni][rr * 2 + cc] * scale;
                        }
                    }
        }
        __syncthreads();
        buf ^= 1;
    }
}

// ============================================================================
// Row softmax: reads fp32 scores from g_S, writes fp16 probs (pair-permuted)
// to g_P. For p in fp16-normal range this equals tf32 rounding (both 11-bit).
// ============================================================================
__global__ __launch_bounds__(128) void softmax_kernel() {
    const int rid = blockIdx.x;
    const int i = rid & (Tq - 1);
    const float* row = g_S + (size_t)rid * Tq;
    __half* rowp = g_P + (size_t)rid * Tq;
    const int len = i + 1;
    const int tx = threadIdx.x;
    const int j0 = tx * 8;

    float vals[8];
    if (j0 < len) {
        float4 v0 = *(const float4*)(row + j0);
        float4 v1 = *(const float4*)(row + j0 + 4);
        vals[0] = v0.x; vals[1] = v0.y; vals[2] = v0.z; vals[3] = v0.w;
        vals[4] = v1.x; vals[5] = v1.y; vals[6] = v1.z; vals[7] = v1.w;
    } else {
#pragma unroll
        for (int u = 0; u < 8; u++) vals[u] = -1e30f;
    }

    float m = -1e30f;
#pragma unroll
    for (int u = 0; u < 8; u++)
        if (j0 + u < len) m = fmaxf(m, vals[u]);

    __shared__ float redm[4];
    __shared__ float reds[4];
#pragma unroll
    for (int o = 16; o; o >>= 1) m = fmaxf(m, __shfl_xor_sync(0xffffffffu, m, o));
    if ((tx & 31) == 0) redm[tx >> 5] = m;
    __syncthreads();
    m = fmaxf(fmaxf(redm[0], redm[1]), fmaxf(redm[2], redm[3]));

    float s = 0.f;
#pragma unroll
    for (int u = 0; u < 8; u++) {
        float e = __expf(vals[u] - m);
        vals[u] = e;
        if (j0 + u < len) s += e;
    }
#pragma unroll
    for (int o = 16; o; o >>= 1) s += __shfl_xor_sync(0xffffffffu, s, o);
    if ((tx & 31) == 0) reds[tx >> 5] = s;
    __syncthreads();
    s = reds[0] + reds[1] + reds[2] + reds[3];
    const float inv = 1.0f / s;

    if (j0 + 8 <= len) {
        // full group: halves in permuted memory order [p0,p4,p1,p5,p2,p6,p3,p7]
        uint4 o;
        o.x = h2u(__floats2half2_rn(vals[0] * inv, vals[4] * inv));
        o.y = h2u(__floats2half2_rn(vals[1] * inv, vals[5] * inv));
        o.z = h2u(__floats2half2_rn(vals[2] * inv, vals[6] * inv));
        o.w = h2u(__floats2half2_rn(vals[3] * inv, vals[7] * inv));
        *(uint4*)(rowp + j0) = o;
    } else if (j0 < len) {
#pragma unroll
        for (int u = 0; u < 8; u++)
            if (j0 + u < len)
                rowp[j0 + perm8(u)] = __float2half_rn(vals[u] * inv);
    }
}

// ============================================================================
// Coverage: out[b][j][i] = mean_n prob[b][n][i][j], reading fp16 g_P.
// Stored half2 at offset (8gg + 2q) = orig cols (8gg+q, 8gg+q+4).
// ============================================================================
__global__ __launch_bounds__(256) void coverage_kernel(float* __restrict__ out_cov) {
    const int b = blockIdx.z;
    const int i0 = blockIdx.y * 32, j0 = blockIdx.x * 32;
    const int tx = threadIdx.x;

    if (j0 >= i0 + 32) {
#pragma unroll
        for (int it = 0; it < 4; it++) {
            int idx = tx + it * 256;
            int jj = idx >> 5, ii = idx & 31;
            out_cov[((size_t)b * Tq + j0 + jj) * Tq + i0 + ii] = 0.f;
        }
        return;
    }

    __shared__ float cs[32][33];
#pragma unroll
    for (int it = 0; it < 2; it++) {
        int idx = tx + it * 256;
        int ii = idx >> 4;           // 0..31
        int pr = idx & 15;           // pair id: 4 groups x 4 pairs
        int gg = pr >> 2, q = pr & 3;
        float s0 = 0.f, s1 = 0.f;
#pragma unroll
        for (int n = 0; n < 16; n++) {
            const __half2 h = *(const __half2*)(g_P +
                (((size_t)(b * 16 + n) * Tq + i0 + ii) * Tq) + j0 + 8 * gg + 2 * q);
            float2 f = __half22float2(h);
            s0 += f.x; s1 += f.y;
        }
        cs[ii][8 * gg + q]     = s0 * (1.0f / 16.0f);
        cs[ii][8 * gg + q + 4] = s1 * (1.0f / 16.0f);
    }
    __syncthreads();
#pragma unroll
    for (int it = 0; it < 4; it++) {
        int idx = tx + it * 256;
        int jj = idx >> 5, ii = idx & 31;
        out_cov[((size_t)b * Tq + j0 + jj) * Tq + i0 + ii] = cs[ii][jj];
    }
}

// ============================================================================
// PV: attn_vec = P @ V. P tiles fp16 from g_P (half traffic/smem).
// P loader: 4 threads/row x 2 CP16 at half-offsets pq*16 + {0,8} => all 64
// halves per row covered (this was the R16 NaN bug).
// smem: P 2x(64*72 halves)=18432B | V 2x(64*72 f32)=36864B -> 55296B
// ============================================================================
#define AVPH (64*72)               /* halves per P stage */
#define AVV  (64*72)               /* floats per V stage */
#define AV_P_BYTES (AVPH * 2)
#define AV_SMEM (2*AV_P_BYTES + 2*AVV*4)   /* 55296 bytes */

__global__ __launch_bounds__(256, 3) void av_kernel() {
    extern __shared__ __align__(16) char avsm[];
    __half* Pf = (__half*)avsm;                       // 2 stages
    float* Vf = (float*)(avsm + 2 * AV_P_BYTES);      // 2 stages
    uint32_t pB = (uint32_t)__cvta_generic_to_shared(Pf);
    uint32_t vB = (uint32_t)__cvta_generic_to_shared(Vf);

    const int ti = (Tq / 64 - 1) - blockIdx.x;
    const int z = blockIdx.y;
    const int bq = z >> 4, nh = z & 15;
    const int tx = threadIdx.x;
    const int warp = tx >> 5, lane = tx & 31;
    const int g = lane >> 2, tg = lane & 3;
    const int wm = (warp >> 2) * 32;
    const int wn = (warp & 3) * 16;

    const int lrow = tx >> 2;                 // 64 rows, 4 thr/row
    const int pq   = tx & 3;
    const int lcf  = pq * 16;                 // V: 16 floats per thread
    const int lph  = pq * 16;                 // P: 16 halves per thread (2 CP16)
    const __half* pbase = g_P + ((size_t)z * Tq + ti * 64 + lrow) * Tq + lph;
    const float*  vbase = g_v + ((size_t)z * Tq + lrow) * DH + lcf;

    const int nj = ti + 1;

    float acc[2][2][4];
#pragma unroll
    for (int mi = 0; mi < 2; mi++)
#pragma unroll
        for (int ni = 0; ni < 2; ni++)
#pragma unroll
            for (int r = 0; r < 4; r++) acc[mi][ni][r] = 0.f;

    // prologue: stage 0 <- j-tile 0
#pragma unroll
    for (int p = 0; p < 2; p++)
        CP16(pB + (uint32_t)(lrow * 72 + lph + p * 8) * 2u, pbase + p * 8);
#pragma unroll
    for (int q = 0; q < 4; q++)
        CP16(vB + (uint32_t)(lrow * 72 + lcf + q * 4) * 4u, vbase + q * 4);
    CP_COMMIT();

    int buf = 0;
#pragma unroll 1
    for (int jt = 0; jt < nj; jt++) {
        if (jt + 1 < nj) {
            int s = buf ^ 1;
            int jn = jt + 1;
#pragma unroll
            for (int p = 0; p < 2; p++)
                CP16(pB + (uint32_t)(s * AVPH + lrow * 72 + lph + p * 8) * 2u,
                     pbase + jn * 64 + p * 8);
#pragma unroll
            for (int q = 0; q < 4; q++)
                CP16(vB + (uint32_t)(s * AVV + lrow * 72 + lcf + q * 4) * 4u,
                     vbase + (size_t)jn * 64 * DH + q * 4);
            CP_COMMIT();
            CP_WAIT(1);
        } else {
            CP_WAIT(0);
        }
        __syncthreads();

        const __half* P = Pf + buf * AVPH;
        const uint32_t* V = (const uint32_t*)(Vf + buf * AVV);
#pragma unroll
        for (int ks = 0; ks < 64; ks += 8) {
            uint32_t a[2][4], b[2][2];
#pragma unroll
            for (int mi = 0; mi < 2; mi++) {
                int r = wm + mi * 16 + g;
                float2 f0 = __half22float2(*(const __half2*)&P[r * 72 + ks + 2 * tg]);
                float2 f1 = __half22float2(*(const __half2*)&P[(r + 8) * 72 + ks + 2 * tg]);
                a[mi][0] = __float_as_uint(f0.x); a[mi][2] = __float_as_uint(f0.y);
                a[mi][1] = __float_as_uint(f1.x); a[mi][3] = __float_as_uint(f1.y);
            }
#pragma unroll
            for (int ni = 0; ni < 2; ni++) {
                int c = wn + ni * 8 + g;
                b[ni][0] = V[(ks + tg) * 72 + c];
                b[ni][1] = V[(ks + tg + 4) * 72 + c];
            }
#pragma unroll
            for (int mi = 0; mi < 2; mi++)
#pragma unroll
                for (int ni = 0; ni < 2; ni++)
                    mma8(acc[mi][ni], a[mi][0], a[mi][1], a[mi][2], a[mi][3],
                         b[ni][0], b[ni][1]);
        }
        __syncthreads();
        buf ^= 1;
    }

#pragma unroll
    for (int mi = 0; mi < 2; mi++)
#pragma unroll
        for (int ni = 0; ni < 2; ni++)
#pragma unroll
            for (int rr = 0; rr < 2; rr++) {
                int i = ti * 64 + wm + mi * 16 + g + rr * 8;
#pragma unroll
                for (int cc = 0; cc < 2; cc++) {
                    int d = wn + ni * 8 + 2 * tg + cc;
                    int dp = (d & ~7) + perm8(d & 7);
                    g_av[((size_t)(i * Bq + bq)) * ND + nh * 64 + dp] = acc[mi][ni][rr * 2 + cc];
                }
            }
}

// ============================================================================
extern "C" void kernel_launch(void* const* d_in, const int* in_sizes, int n_in,
                              void* d_out, int out_size) {
    const float* inp  = (const float*)d_in[0];
    const float* pe   = (const float*)d_in[1];
    const float* Wqkv = (const float*)d_in[3];
    const float* Wo   = (const float*)d_in[4];

    float* out_attn = (float*)d_out;
    float* out_cov  = out_attn + (size_t)TB * ND;

    cudaFuncSetAttribute(qkv_gemm, cudaFuncAttributeMaxDynamicSharedMemorySize, GEMM_SMEM);
    cudaFuncSetAttribute(out_gemm, cudaFuncAttributeMaxDynamicSharedMemorySize, GEMM_SMEM);
    cudaFuncSetAttribute(av_kernel, cudaFuncAttributeMaxDynamicSharedMemorySize, AV_SMEM);
    cudaFuncSetAttribute(score_kernel, cudaFuncAttributeMaxDynamicSharedMemorySize, SC_SMEM);

    add_kernel<<<TB * Dq / 2048, 256>>>(inp, pe);
    round_wq<<<dim3(N3 / 32, Dq / 32), 256>>>(Wqkv);
    round_wo<<<dim3(ND / 32, ND / 32), 256>>>(Wo);
    qkv_gemm<<<dim3(N3 / 128, TB / 128), 256, GEMM_SMEM>>>();
    score_kernel<<<dim3(Tq / 64, ZN), 256, SC_SMEM>>>();
    softmax_kernel<<<ZN * Tq, 128>>>();
    coverage_kernel<<<dim3(Tq / 32, Tq / 32, Bq), 256>>>(out_cov);
    av_kernel<<<dim3(Tq / 64, ZN), 256, AV_SMEM>>>();
    out_gemm<<<dim3(ND / 128, TB / 128), 256, GEMM_SMEM>>>(out_attn);
}